// round 8
// baseline (speedup 1.0000x reference)
#include <cuda_runtime.h>
#include <cuda_bf16.h>
#include <cstdint>

// Problem constants (fixed by the dataset)
#define SEQ_TOTAL 2048
#define SEQ_EVAL  1024
#define NBATCH    128
#define NFEAT     256

// ---------------- device scratch (static; no allocation) ----------------
__device__ __align__(16) __nv_bfloat16 g_xn[(size_t)NBATCH * NFEAT * SEQ_EVAL]; // [b][f][s] bf16, 64MB
__device__ float g_m2[NBATCH * NFEAT];
__device__ int   g_colsum[NBATCH * NFEAT];
__device__ int   g_order[NBATCH * NFEAT];
__device__ int   g_count[NBATCH];

// ---------------- helpers ----------------
__device__ __forceinline__ unsigned smem_u32(const void* p) {
    return (unsigned)__cvta_generic_to_shared(p);
}

__device__ __forceinline__ void ldm_x4(unsigned& r0, unsigned& r1, unsigned& r2,
                                       unsigned& r3, unsigned addr) {
    asm volatile("ldmatrix.sync.aligned.m8n8.x4.shared.b16 {%0,%1,%2,%3}, [%4];"
                 : "=r"(r0), "=r"(r1), "=r"(r2), "=r"(r3) : "r"(addr));
}

__device__ __forceinline__ void mma_bf16(float* c, const unsigned* a, const unsigned* bf) {
    asm volatile(
        "mma.sync.aligned.m16n8k16.row.col.f32.bf16.bf16.f32 "
        "{%0,%1,%2,%3}, {%4,%5,%6,%7}, {%8,%9}, {%0,%1,%2,%3};"
        : "+f"(c[0]), "+f"(c[1]), "+f"(c[2]), "+f"(c[3])
        : "r"(a[0]), "r"(a[1]), "r"(a[2]), "r"(a[3]), "r"(bf[0]), "r"(bf[1]));
}

// ======================================================================
// Kernel 1: per-(b,f) mean/std over s<1024, then clip-normalize,
// accumulate m2 (mean of clipped), transpose-store bf16 to [b][f][s].
// Also zeroes colsum.
// ======================================================================
__global__ void __launch_bounds__(256) stats_kernel(const float* __restrict__ x) {
    const int b = blockIdx.x;
    const int f = threadIdx.x;
    const float* xp = x + (size_t)b * NFEAT + f;
    const size_t stride = (size_t)NBATCH * NFEAT;

    float s0=0,s1=0,s2=0,s3=0,s4=0,s5=0,s6=0,s7=0;
    float q0=0,q1=0,q2=0,q3=0,q4=0,q5=0,q6=0,q7=0;
    for (int s = 0; s < SEQ_EVAL; s += 8) {
        float v0 = xp[(size_t)(s+0)*stride];
        float v1 = xp[(size_t)(s+1)*stride];
        float v2 = xp[(size_t)(s+2)*stride];
        float v3 = xp[(size_t)(s+3)*stride];
        float v4 = xp[(size_t)(s+4)*stride];
        float v5 = xp[(size_t)(s+5)*stride];
        float v6 = xp[(size_t)(s+6)*stride];
        float v7 = xp[(size_t)(s+7)*stride];
        s0+=v0; q0+=v0*v0;  s1+=v1; q1+=v1*v1;
        s2+=v2; q2+=v2*v2;  s3+=v3; q3+=v3*v3;
        s4+=v4; q4+=v4*v4;  s5+=v5; q5+=v5*v5;
        s6+=v6; q6+=v6*v6;  s7+=v7; q7+=v7*v7;
    }
    float sum = ((s0+s1)+(s2+s3)) + ((s4+s5)+(s6+s7));
    float sq  = ((q0+q1)+(q2+q3)) + ((q4+q5)+(q6+q7));
    float mean = sum * (1.0f / SEQ_EVAL);
    float var = (sq - (float)SEQ_EVAL * mean * mean) * (1.0f / (SEQ_EVAL - 1));
    var = fmaxf(var, 0.0f);
    float inv = 1.0f / (sqrtf(var) + 1e-6f);

    // pass 2: clip-normalize, transpose via shared, write bf16 scratch [b][f][s]
    __shared__ __nv_bfloat16 tile[64][258];
    float m2a = 0.0f;
    unsigned* outb = reinterpret_cast<unsigned*>(g_xn) + (size_t)b * NFEAT * (SEQ_EVAL / 2);
    for (int c = 0; c < 16; c++) {
        const int sb = c * 64;
        #pragma unroll 4
        for (int sl = 0; sl < 64; sl++) {
            float v = xp[(size_t)(sb + sl) * stride];
            float z = (v - mean) * inv;
            z = fminf(fmaxf(z, -100.0f), 100.0f);
            m2a += z;
            tile[sl][f] = __float2bfloat16(z);
        }
        __syncthreads();
        #pragma unroll 4
        for (int it = 0; it < 32; it++) {
            int idx = it * 256 + threadIdx.x;
            int ff = idx >> 5;
            int sp = idx & 31;
            unsigned lo = __bfloat16_as_ushort(tile[2*sp][ff]);
            unsigned hi = __bfloat16_as_ushort(tile[2*sp+1][ff]);
            outb[(size_t)ff * (SEQ_EVAL/2) + (sb >> 1) + sp] = (hi << 16) | lo;
        }
        __syncthreads();
    }
    g_m2[b * NFEAT + f] = m2a * (1.0f / SEQ_EVAL);
    g_colsum[b * NFEAT + f] = 0;
}

// ======================================================================
// Kernel 2: Gram via mma.sync bf16 (HMMA). Grid = (2 M-halves, 128 batches).
// CTA: 512 threads = 16 warps (4 along M x 4 along N). Warp tile 32x64.
// One shared 256-row x 128B K-chunk tile serves both A (subset rows) and B.
// Epilogue: cov = (G - n*m2_i*m2_j)/(n-1), threshold, triu colsum via atomics.
// ======================================================================
__global__ void __launch_bounds__(512) gram_kernel() {
    __shared__ __align__(1024) unsigned char tileB[256 * 128];  // 32 KB
    __shared__ float m2sh[NFEAT];

    const int mh = blockIdx.x;      // 0/1 -> feature rows [mh*128, mh*128+128)
    const int b  = blockIdx.y;
    const int tid = threadIdx.x;
    const int wid = tid >> 5;
    const int lane = tid & 31;
    const int wm = wid >> 2;        // 0..3 : 32-row group within the 128 M rows
    const int wn = wid & 3;         // 0..3 : 64-col group within 256 N cols

    if (tid < NFEAT) m2sh[tid] = g_m2[b * NFEAT + tid];

    const unsigned smB = smem_u32(tileB);
    const uint4* __restrict__ xsrc =
        reinterpret_cast<const uint4*>(g_xn) + (size_t)b * NFEAT * 128;  // 128 uint4 per feature row

    float acc[2][8][4];
    #pragma unroll
    for (int mt = 0; mt < 2; mt++)
        #pragma unroll
        for (int nt = 0; nt < 8; nt++)
            #pragma unroll
            for (int r = 0; r < 4; r++) acc[mt][nt][r] = 0.0f;

    // precomputed ldmatrix address components
    const int a_row_in_tile0 = mh * 128 + wm * 32 + (lane & 15);  // + mt*16
    const unsigned a_kadd = (lane >> 4) * 16;
    const int bg = lane >> 3;
    const int b_row0 = wn * 64 + ((bg >> 1) << 3) + (lane & 7);    // + nt2*16
    const unsigned b_kadd = (bg & 1) * 16;

    for (int t = 0; t < 16; t++) {
        const int kq = t * 8;  // uint4 offset within feature row (64 bf16 per chunk)
        // stage 256 rows x 128B of this K-chunk
        #pragma unroll
        for (int i = 0; i < 4; i++) {
            int idx = i * 512 + tid;
            int row = idx >> 3, seg = idx & 7;
            uint4 v = xsrc[(size_t)row * 128 + kq + seg];
            unsigned off = row * 128 + seg * 16;
            off ^= (off >> 3) & 0x70;
            *reinterpret_cast<uint4*>(tileB + off) = v;
        }
        __syncthreads();

        #pragma unroll
        for (int ks = 0; ks < 4; ks++) {
            unsigned a[2][4];
            #pragma unroll
            for (int mt = 0; mt < 2; mt++) {
                unsigned off = (unsigned)(a_row_in_tile0 + mt * 16) * 128 + ks * 32 + a_kadd;
                off ^= (off >> 3) & 0x70;
                ldm_x4(a[mt][0], a[mt][1], a[mt][2], a[mt][3], smB + off);
            }
            #pragma unroll
            for (int nt2 = 0; nt2 < 4; nt2++) {
                unsigned bb[4];
                unsigned off = (unsigned)(b_row0 + nt2 * 16) * 128 + ks * 32 + b_kadd;
                off ^= (off >> 3) & 0x70;
                ldm_x4(bb[0], bb[1], bb[2], bb[3], smB + off);
                mma_bf16(acc[0][nt2 * 2 + 0], a[0], bb + 0);
                mma_bf16(acc[0][nt2 * 2 + 1], a[0], bb + 2);
                mma_bf16(acc[1][nt2 * 2 + 0], a[1], bb + 0);
                mma_bf16(acc[1][nt2 * 2 + 1], a[1], bb + 2);
            }
        }
        __syncthreads();
    }

    // epilogue: threshold + triu column-sum
    const float inv_nm1 = 1.0f / (SEQ_EVAL - 1);
    #pragma unroll
    for (int mt = 0; mt < 2; mt++) {
        const int i_lo = mh * 128 + wm * 32 + mt * 16 + (lane >> 2);
        const int i_hi = i_lo + 8;
        const float m2lo = m2sh[i_lo] * (float)SEQ_EVAL;
        const float m2hi = m2sh[i_hi] * (float)SEQ_EVAL;
        #pragma unroll
        for (int nt = 0; nt < 8; nt++) {
            const int j0 = wn * 64 + nt * 8 + ((lane & 3) << 1);
            const float mj0 = m2sh[j0], mj1 = m2sh[j0 + 1];
            float c00 = (acc[mt][nt][0] - m2lo * mj0) * inv_nm1;
            float c01 = (acc[mt][nt][1] - m2lo * mj1) * inv_nm1;
            float c10 = (acc[mt][nt][2] - m2hi * mj0) * inv_nm1;
            float c11 = (acc[mt][nt][3] - m2hi * mj1) * inv_nm1;
            if (i_lo <= j0     && c00 > 0.999f) atomicAdd(&g_colsum[b * NFEAT + j0],     1);
            if (i_lo <= j0 + 1 && c01 > 0.999f) atomicAdd(&g_colsum[b * NFEAT + j0 + 1], 1);
            if (i_hi <= j0     && c10 > 0.999f) atomicAdd(&g_colsum[b * NFEAT + j0],     1);
            if (i_hi <= j0 + 1 && c11 > 0.999f) atomicAdd(&g_colsum[b * NFEAT + j0 + 1], 1);
        }
    }
}

// ======================================================================
// Kernel 3: per-batch stable partition -> order + counts
// ======================================================================
__global__ void __launch_bounds__(256) select_kernel() {
    const int b = blockIdx.x;
    const int f = threadIdx.x;
    const int wid = f >> 5, lane = f & 31;
    bool sel = (g_colsum[b * NFEAT + f] == 1);
    unsigned m = __ballot_sync(0xFFFFFFFFu, sel);
    int wpre = __popc(m & ((1u << lane) - 1u));
    __shared__ int wtot[8], wbase[8], total;
    if (lane == 0) wtot[wid] = __popc(m);
    __syncthreads();
    if (f == 0) {
        int acc = 0;
        for (int w = 0; w < 8; w++) { wbase[w] = acc; acc += wtot[w]; }
        total = acc;
    }
    __syncthreads();
    int selpre = wbase[wid] + wpre;             // #selected with index < f
    int pos = sel ? selpre : (total + f - selpre);
    g_order[b * NFEAT + pos] = f;
    if (f == 0) g_count[b] = total;
}

// ======================================================================
// Kernel 4: gather + keep-mask over the full sequence
// ======================================================================
__global__ void __launch_bounds__(256) gather_kernel(const float* __restrict__ x,
                                                     float* __restrict__ out) {
    const int b = blockIdx.y;
    const int sg = blockIdx.x;
    const int f = threadIdx.x;
    __shared__ int osh[256];
    __shared__ int cnt;
    osh[f] = g_order[b * NFEAT + f];
    if (f == 0) cnt = g_count[b];
    __syncthreads();
    const int src = osh[f];
    const bool keep = f < cnt;
    #pragma unroll 4
    for (int si = 0; si < 32; si++) {
        size_t base = ((size_t)(sg * 32 + si) * NBATCH + b) * NFEAT;
        out[base + f] = keep ? x[base + src] : 0.0f;
    }
}

// ======================================================================
extern "C" void kernel_launch(void* const* d_in, const int* in_sizes, int n_in,
                              void* d_out, int out_size) {
    (void)in_sizes; (void)n_in; (void)out_size;
    const float* x = (const float*)d_in[0];
    float* out = (float*)d_out;

    stats_kernel<<<NBATCH, 256>>>(x);
    gram_kernel<<<dim3(2, NBATCH), 512>>>();
    select_kernel<<<NBATCH, 256>>>();
    gather_kernel<<<dim3(SEQ_TOTAL / 32, NBATCH), 256>>>(x, out);
}

// round 13
// speedup vs baseline: 1.7860x; 1.7860x over previous
#include <cuda_runtime.h>
#include <cuda_bf16.h>
#include <cstdint>

// Problem constants (fixed by the dataset)
#define SEQ_TOTAL 2048
#define SEQ_EVAL  1024
#define NBATCH    128
#define NFEAT     256
#define NSCHUNK   8           // s-chunks for stats/normalize split (1024/8 = 128 rows each)

// ---------------- device scratch (static; no allocation) ----------------
__device__ __align__(16) __nv_bfloat16 g_xn[(size_t)NBATCH * NFEAT * SEQ_EVAL]; // [b][f][s] bf16
__device__ float g_sumpart[NBATCH * NSCHUNK * NFEAT];
__device__ float g_sqpart [NBATCH * NSCHUNK * NFEAT];
__device__ float g_m2part [NBATCH * NSCHUNK * NFEAT];
__device__ float g_mean[NBATCH * NFEAT];
__device__ float g_inv [NBATCH * NFEAT];
__device__ int   g_colsum[NBATCH * NFEAT];
__device__ int   g_order[NBATCH * NFEAT];
__device__ int   g_count[NBATCH];

// ---------------- helpers ----------------
__device__ __forceinline__ unsigned smem_u32(const void* p) {
    return (unsigned)__cvta_generic_to_shared(p);
}

__device__ __forceinline__ void ldm_x4(unsigned& r0, unsigned& r1, unsigned& r2,
                                       unsigned& r3, unsigned addr) {
    asm volatile("ldmatrix.sync.aligned.m8n8.x4.shared.b16 {%0,%1,%2,%3}, [%4];"
                 : "=r"(r0), "=r"(r1), "=r"(r2), "=r"(r3) : "r"(addr));
}

__device__ __forceinline__ void mma_bf16(float* c, const unsigned* a, const unsigned* bf) {
    asm volatile(
        "mma.sync.aligned.m16n8k16.row.col.f32.bf16.bf16.f32 "
        "{%0,%1,%2,%3}, {%4,%5,%6,%7}, {%8,%9}, {%0,%1,%2,%3};"
        : "+f"(c[0]), "+f"(c[1]), "+f"(c[2]), "+f"(c[3])
        : "r"(a[0]), "r"(a[1]), "r"(a[2]), "r"(a[3]), "r"(bf[0]), "r"(bf[1]));
}

__device__ __forceinline__ void cp_async16(unsigned saddr, const void* gptr) {
    asm volatile("cp.async.cg.shared.global [%0], [%1], 16;"
                 :: "r"(saddr), "l"(gptr) : "memory");
}

// ======================================================================
// Kernel 1a: partial sum/sumsq over an s-chunk of 128 rows.
// Grid (NBATCH, NSCHUNK) = 1024 CTAs, 256 threads (one per feature).
// ======================================================================
__global__ void __launch_bounds__(256) partial_stats_kernel(const float* __restrict__ x) {
    const int b = blockIdx.x;
    const int c = blockIdx.y;
    const int f = threadIdx.x;
    const size_t stride = (size_t)NBATCH * NFEAT;
    const float* xp = x + (size_t)(c * 128) * stride + (size_t)b * NFEAT + f;

    float s = 0.0f, q = 0.0f;
    #pragma unroll 8
    for (int i = 0; i < 128; i++) {
        float v = xp[(size_t)i * stride];
        s += v; q += v * v;
    }
    g_sumpart[(b * NSCHUNK + c) * NFEAT + f] = s;
    g_sqpart [(b * NSCHUNK + c) * NFEAT + f] = q;
}

// ======================================================================
// Kernel 1b: finalize mean/inv-std, zero colsum. Grid (NBATCH), 256 thr.
// ======================================================================
__global__ void __launch_bounds__(256) finalize_stats_kernel() {
    const int b = blockIdx.x;
    const int f = threadIdx.x;
    float s = 0.0f, q = 0.0f;
    #pragma unroll
    for (int c = 0; c < NSCHUNK; c++) {
        s += g_sumpart[(b * NSCHUNK + c) * NFEAT + f];
        q += g_sqpart [(b * NSCHUNK + c) * NFEAT + f];
    }
    float mean = s * (1.0f / SEQ_EVAL);
    float var = (q - (float)SEQ_EVAL * mean * mean) * (1.0f / (SEQ_EVAL - 1));
    var = fmaxf(var, 0.0f);
    float inv = 1.0f / (sqrtf(var) + 1e-6f);
    g_mean[b * NFEAT + f] = mean;
    g_inv [b * NFEAT + f] = inv;
    g_colsum[b * NFEAT + f] = 0;
}

// ======================================================================
// Kernel 1c: clip-normalize an s-chunk of 128 rows, transpose-store bf16
// to g_xn [b][f][s], accumulate partial m2 (sum of z).
// Grid (NBATCH, NSCHUNK) = 1024 CTAs, 256 threads.
// ======================================================================
__global__ void __launch_bounds__(256) normalize_kernel(const float* __restrict__ x) {
    const int b  = blockIdx.x;
    const int sc = blockIdx.y;
    const int f  = threadIdx.x;
    const size_t stride = (size_t)NBATCH * NFEAT;
    const int s0 = sc * 128;
    const float* xp = x + (size_t)s0 * stride + (size_t)b * NFEAT + f;

    const float mean = g_mean[b * NFEAT + f];
    const float inv  = g_inv [b * NFEAT + f];

    __shared__ __nv_bfloat16 tile[64][258];
    float m2a = 0.0f;
    unsigned* outb = reinterpret_cast<unsigned*>(g_xn) + (size_t)b * NFEAT * (SEQ_EVAL / 2);

    for (int c2 = 0; c2 < 2; c2++) {
        const int sb = c2 * 64;
        #pragma unroll 4
        for (int sl = 0; sl < 64; sl++) {
            float v = xp[(size_t)(sb + sl) * stride];
            float z = (v - mean) * inv;
            z = fminf(fmaxf(z, -100.0f), 100.0f);
            m2a += z;
            tile[sl][f] = __float2bfloat16(z);
        }
        __syncthreads();
        #pragma unroll 4
        for (int it = 0; it < 32; it++) {
            int idx = it * 256 + threadIdx.x;
            int ff = idx >> 5;
            int sp = idx & 31;
            unsigned lo = __bfloat16_as_ushort(tile[2 * sp][ff]);
            unsigned hi = __bfloat16_as_ushort(tile[2 * sp + 1][ff]);
            outb[(size_t)ff * (SEQ_EVAL / 2) + ((s0 + sb) >> 1) + sp] = (hi << 16) | lo;
        }
        __syncthreads();
    }
    g_m2part[(b * NSCHUNK + sc) * NFEAT + f] = m2a;
}

// ======================================================================
// Kernel 2: Gram via mma.sync bf16, double-buffered cp.async pipeline.
// Grid = (2 M-halves, 128 batches). 512 threads = 16 warps (4M x 4N).
// Dynamic smem: 2 x 32KB tiles + 1KB m2sh.
// ======================================================================
#define GK_TILE_BYTES 32768
#define GK_SMEM_BYTES (2 * GK_TILE_BYTES + NFEAT * 4)

__global__ void __launch_bounds__(512) gram_kernel() {
    extern __shared__ __align__(1024) unsigned char dynsm[];
    unsigned char* tiles = dynsm;                          // 2 x 32KB
    float* m2sh = reinterpret_cast<float*>(dynsm + 2 * GK_TILE_BYTES);

    const int mh = blockIdx.x;
    const int b  = blockIdx.y;
    const int tid = threadIdx.x;
    const int wid = tid >> 5;
    const int lane = tid & 31;
    const int wm = wid >> 2;
    const int wn = wid & 3;

    // m2 = (sum of z)/n, reduced from partials
    if (tid < NFEAT) {
        float s = 0.0f;
        #pragma unroll
        for (int c = 0; c < NSCHUNK; c++) s += g_m2part[(b * NSCHUNK + c) * NFEAT + tid];
        m2sh[tid] = s * (1.0f / SEQ_EVAL);
    }

    const unsigned smBase = smem_u32(tiles);
    const uint4* __restrict__ xsrc =
        reinterpret_cast<const uint4*>(g_xn) + (size_t)b * NFEAT * 128;

    float acc[2][8][4];
    #pragma unroll
    for (int mt = 0; mt < 2; mt++)
        #pragma unroll
        for (int nt = 0; nt < 8; nt++)
            #pragma unroll
            for (int r = 0; r < 4; r++) acc[mt][nt][r] = 0.0f;

    const int a_row_in_tile0 = mh * 128 + wm * 32 + (lane & 15);
    const unsigned a_kadd = (lane >> 4) * 16;
    const int bg = lane >> 3;
    const int b_row0 = wn * 64 + ((bg >> 1) << 3) + (lane & 7);
    const unsigned b_kadd = (bg & 1) * 16;

    // issue one 32KB tile (256 rows x 128B) into buffer `buf` for K-step t
    auto issue_tile = [&](int t, int buf) {
        const int kq = t * 8;
        const unsigned base = smBase + buf * GK_TILE_BYTES;
        #pragma unroll
        for (int i = 0; i < 4; i++) {
            int idx = i * 512 + tid;
            int row = idx >> 3, seg = idx & 7;
            unsigned off = row * 128 + seg * 16;
            off ^= (off >> 3) & 0x70;
            cp_async16(base + off, xsrc + (size_t)row * 128 + kq + seg);
        }
        asm volatile("cp.async.commit_group;" ::: "memory");
    };

    issue_tile(0, 0);

    for (int t = 0; t < 16; t++) {
        if (t < 15) {
            issue_tile(t + 1, (t + 1) & 1);
            asm volatile("cp.async.wait_group 1;" ::: "memory");
        } else {
            asm volatile("cp.async.wait_group 0;" ::: "memory");
        }
        __syncthreads();

        const unsigned curr = smBase + (t & 1) * GK_TILE_BYTES;
        #pragma unroll
        for (int ks = 0; ks < 4; ks++) {
            unsigned a[2][4];
            #pragma unroll
            for (int mt = 0; mt < 2; mt++) {
                unsigned off = (unsigned)(a_row_in_tile0 + mt * 16) * 128 + ks * 32 + a_kadd;
                off ^= (off >> 3) & 0x70;
                ldm_x4(a[mt][0], a[mt][1], a[mt][2], a[mt][3], curr + off);
            }
            #pragma unroll
            for (int nt2 = 0; nt2 < 4; nt2++) {
                unsigned bb[4];
                unsigned off = (unsigned)(b_row0 + nt2 * 16) * 128 + ks * 32 + b_kadd;
                off ^= (off >> 3) & 0x70;
                ldm_x4(bb[0], bb[1], bb[2], bb[3], curr + off);
                mma_bf16(acc[0][nt2 * 2 + 0], a[0], bb + 0);
                mma_bf16(acc[0][nt2 * 2 + 1], a[0], bb + 2);
                mma_bf16(acc[1][nt2 * 2 + 0], a[1], bb + 0);
                mma_bf16(acc[1][nt2 * 2 + 1], a[1], bb + 2);
            }
        }
        __syncthreads();
    }

    // epilogue: threshold + triu column-sum
    const float inv_nm1 = 1.0f / (SEQ_EVAL - 1);
    #pragma unroll
    for (int mt = 0; mt < 2; mt++) {
        const int i_lo = mh * 128 + wm * 32 + mt * 16 + (lane >> 2);
        const int i_hi = i_lo + 8;
        const float m2lo = m2sh[i_lo] * (float)SEQ_EVAL;
        const float m2hi = m2sh[i_hi] * (float)SEQ_EVAL;
        #pragma unroll
        for (int nt = 0; nt < 8; nt++) {
            const int j0 = wn * 64 + nt * 8 + ((lane & 3) << 1);
            const float mj0 = m2sh[j0], mj1 = m2sh[j0 + 1];
            float c00 = (acc[mt][nt][0] - m2lo * mj0) * inv_nm1;
            float c01 = (acc[mt][nt][1] - m2lo * mj1) * inv_nm1;
            float c10 = (acc[mt][nt][2] - m2hi * mj0) * inv_nm1;
            float c11 = (acc[mt][nt][3] - m2hi * mj1) * inv_nm1;
            if (i_lo <= j0     && c00 > 0.999f) atomicAdd(&g_colsum[b * NFEAT + j0],     1);
            if (i_lo <= j0 + 1 && c01 > 0.999f) atomicAdd(&g_colsum[b * NFEAT + j0 + 1], 1);
            if (i_hi <= j0     && c10 > 0.999f) atomicAdd(&g_colsum[b * NFEAT + j0],     1);
            if (i_hi <= j0 + 1 && c11 > 0.999f) atomicAdd(&g_colsum[b * NFEAT + j0 + 1], 1);
        }
    }
}

// ======================================================================
// Kernel 3: per-batch stable partition -> order + counts
// ======================================================================
__global__ void __launch_bounds__(256) select_kernel() {
    const int b = blockIdx.x;
    const int f = threadIdx.x;
    const int wid = f >> 5, lane = f & 31;
    bool sel = (g_colsum[b * NFEAT + f] == 1);
    unsigned m = __ballot_sync(0xFFFFFFFFu, sel);
    int wpre = __popc(m & ((1u << lane) - 1u));
    __shared__ int wtot[8], wbase[8], total;
    if (lane == 0) wtot[wid] = __popc(m);
    __syncthreads();
    if (f == 0) {
        int acc = 0;
        for (int w = 0; w < 8; w++) { wbase[w] = acc; acc += wtot[w]; }
        total = acc;
    }
    __syncthreads();
    int selpre = wbase[wid] + wpre;
    int pos = sel ? selpre : (total + f - selpre);
    g_order[b * NFEAT + pos] = f;
    if (f == 0) g_count[b] = total;
}

// ======================================================================
// Kernel 4: gather + keep-mask over the full sequence (at DRAM floor)
// ======================================================================
__global__ void __launch_bounds__(256) gather_kernel(const float* __restrict__ x,
                                                     float* __restrict__ out) {
    const int b = blockIdx.y;
    const int sg = blockIdx.x;
    const int f = threadIdx.x;
    __shared__ int osh[256];
    __shared__ int cnt;
    osh[f] = g_order[b * NFEAT + f];
    if (f == 0) cnt = g_count[b];
    __syncthreads();
    const int src = osh[f];
    const bool keep = f < cnt;
    #pragma unroll 4
    for (int si = 0; si < 32; si++) {
        size_t base = ((size_t)(sg * 32 + si) * NBATCH + b) * NFEAT;
        out[base + f] = keep ? x[base + src] : 0.0f;
    }
}

// ======================================================================
extern "C" void kernel_launch(void* const* d_in, const int* in_sizes, int n_in,
                              void* d_out, int out_size) {
    (void)in_sizes; (void)n_in; (void)out_size;
    const float* x = (const float*)d_in[0];
    float* out = (float*)d_out;

    partial_stats_kernel<<<dim3(NBATCH, NSCHUNK), 256>>>(x);
    finalize_stats_kernel<<<NBATCH, 256>>>();
    normalize_kernel<<<dim3(NBATCH, NSCHUNK), 256>>>(x);

    cudaFuncSetAttribute(gram_kernel, cudaFuncAttributeMaxDynamicSharedMemorySize,
                         GK_SMEM_BYTES);
    gram_kernel<<<dim3(2, NBATCH), 512, GK_SMEM_BYTES>>>();

    select_kernel<<<NBATCH, 256>>>();
    gather_kernel<<<dim3(SEQ_TOTAL / 32, NBATCH), 256>>>(x, out);
}